// round 14
// baseline (speedup 1.0000x reference)
#include <cuda_runtime.h>
#include <cuda_fp16.h>
#include <math.h>
#include <stdint.h>

#define NDIM 20000
#define DDIM 3072
#define BDIM 128
#define KB 32
#define CH1 (DDIM / KB)            /* 96 */
#define NT1 ((NDIM + 63) / 64)     /* 313 */
#define NSPLIT 6
#define SPAN2 3360                 /* splits 0-4: 105 chunks of 32; split 5: 3200 -> 100 */
#define DT2 (DDIM / 64)            /* 48 */

// GEMM1 smem: per buffer 2 A-splits (128x32 fp16 = 8KB) + 2 B-splits (64x32 = 4KB)
#define SA1(s, p) ((p) * 24576 + (s) * 8192)
#define SB1(s, p) ((p) * 24576 + 16384 + (s) * 4096)
#define SM1_TOTAL (2 * 24576)
// GEMM2 smem: per buffer 1 E tile (8KB) + 1 G tile (4KB)
#define SE2(p) ((p) * 12288)
#define SG2(p) ((p) * 12288 + 8192)
#define SM2_TOTAL (2 * 12288)

// Scratch (allocation-free rule: __device__ globals)
__device__ float g_s[BDIM * NDIM];               // logits
__device__ float g_rowsum[BDIM];
__device__ __half g_eh[BDIM * NDIM];             // e = exp(s - m) in fp16
__device__ float g_part[NSPLIT * BDIM * DDIM];

// Swizzled byte offset inside a [rows x 32k] fp16 tile (row stride 64B).
__device__ __forceinline__ int toff(int row, int k)
{
    return row * 64 + ((((k >> 3) & 3) ^ ((row >> 1) & 3)) << 4) + ((k * 2) & 15);
}

__device__ __forceinline__ uint32_t pk2h(float a, float b)
{
    __half2 t = __floats2half2_rn(a, b);
    return *reinterpret_cast<uint32_t*>(&t);
}
__device__ __forceinline__ void split2h_u4(const float v[8], uint4& uh, uint4& ul)
{
    float h[8], l[8];
#pragma unroll
    for (int i = 0; i < 8; i++) {
        h[i] = __half2float(__float2half_rn(v[i]));
        l[i] = v[i] - h[i];
    }
    uh = make_uint4(pk2h(h[0], h[1]), pk2h(h[2], h[3]), pk2h(h[4], h[5]), pk2h(h[6], h[7]));
    ul = make_uint4(pk2h(l[0], l[1]), pk2h(l[2], l[3]), pk2h(l[4], l[5]), pk2h(l[6], l[7]));
}
__device__ __forceinline__ void mma_f32acc(float c[4], const uint32_t a[4], const uint32_t b[2])
{
    asm volatile(
        "mma.sync.aligned.m16n8k16.row.col.f32.f16.f16.f32 "
        "{%0,%1,%2,%3}, {%4,%5,%6,%7}, {%8,%9}, {%0,%1,%2,%3};"
        : "+f"(c[0]), "+f"(c[1]), "+f"(c[2]), "+f"(c[3])
        : "r"(a[0]), "r"(a[1]), "r"(a[2]), "r"(a[3]), "r"(b[0]), "r"(b[1]));
}
__device__ __forceinline__ void mma_f16acc(uint32_t c[2], const uint32_t a[4], const uint32_t b[2])
{
    asm volatile(
        "mma.sync.aligned.m16n8k16.row.col.f16.f16.f16.f16 "
        "{%0,%1}, {%2,%3,%4,%5}, {%6,%7}, {%0,%1};"
        : "+r"(c[0]), "+r"(c[1])
        : "r"(a[0]), "r"(a[1]), "r"(a[2]), "r"(a[3]), "r"(b[0]), "r"(b[1]));
}
__device__ __forceinline__ float lo2f(uint32_t u) { return __low2float(*reinterpret_cast<__half2*>(&u)); }
__device__ __forceinline__ float hi2f(uint32_t u) { return __high2float(*reinterpret_cast<__half2*>(&u)); }

#define LOAD_AFRAGS(SRC)                                                       \
    do {                                                                       \
        _Pragma("unroll")                                                      \
        for (int mt = 0; mt < 2; mt++)                                         \
            _Pragma("unroll")                                                  \
            for (int ks = 0; ks < 2; ks++) {                                   \
                const int row = wm + mt * 16 + (lane >> 2);                    \
                const int kq = ks * 16 + (lane & 3) * 2;                       \
                af[mt][ks][0] = *(const uint32_t*)((SRC) + toff(row, kq));     \
                af[mt][ks][1] = *(const uint32_t*)((SRC) + toff(row + 8, kq)); \
                af[mt][ks][2] = *(const uint32_t*)((SRC) + toff(row, kq + 8)); \
                af[mt][ks][3] = *(const uint32_t*)((SRC) + toff(row + 8, kq + 8)); \
            }                                                                  \
    } while (0)

#define MMA_PASS_F32(BSRC)                                                     \
    do {                                                                       \
        _Pragma("unroll")                                                      \
        for (int ks = 0; ks < 2; ks++)                                         \
            _Pragma("unroll")                                                  \
            for (int nt = 0; nt < 4; nt++) {                                   \
                const int col = wn + nt * 8 + (lane >> 2);                     \
                const int kq = ks * 16 + (lane & 3) * 2;                       \
                uint32_t bf[2];                                                \
                bf[0] = *(const uint32_t*)((BSRC) + toff(col, kq));            \
                bf[1] = *(const uint32_t*)((BSRC) + toff(col, kq + 8));        \
                _Pragma("unroll")                                              \
                for (int mt = 0; mt < 2; mt++) mma_f32acc(acc[mt][nt], af[mt][ks], bf); \
            }                                                                  \
    } while (0)

#define MMA_PASS_F16(BSRC)                                                     \
    do {                                                                       \
        _Pragma("unroll")                                                      \
        for (int ks = 0; ks < 2; ks++)                                         \
            _Pragma("unroll")                                                  \
            for (int nt = 0; nt < 4; nt++) {                                   \
                const int col = wn + nt * 8 + (lane >> 2);                     \
                const int kq = ks * 16 + (lane & 3) * 2;                       \
                uint32_t bf[2];                                                \
                bf[0] = *(const uint32_t*)((BSRC) + toff(col, kq));            \
                bf[1] = *(const uint32_t*)((BSRC) + toff(col, kq + 8));        \
                _Pragma("unroll")                                              \
                for (int mt = 0; mt < 2; mt++) mma_f16acc(ach[mt][nt], af[mt][ks], bf); \
            }                                                                  \
    } while (0)

// ---------------------------------------------------------------------------
// GEMM1: s[b,n] = alpha[b]*(x_b.gt_n) - beta[b]*||gt_n||^2
// CTA tile 128b x 64n, KB=32, double-buffered, fused alpha/beta/g2 epilogue.
// 3 passes: hh (f32 acc) + hl, lh (f16 acc) — required (alpha amplification).
// ---------------------------------------------------------------------------
__global__ __launch_bounds__(256, 2) void gemm1_kernel(const float* __restrict__ x,
                                                       const float* __restrict__ t,
                                                       const float* __restrict__ gt)
{
    extern __shared__ char sm[];
    __shared__ float alpha_s[128], beta_s[128], g2s[64];

    const int tid = threadIdx.x, lane = tid & 31, warp = tid >> 5;
    const int wm = (warp & 3) * 32, wn = (warp >> 2) * 32;
    const int nblk = blockIdx.x * 64;

    if (tid < 128) {
        const float tt = t[tid] * (1.0f / 999.0f);
        const float sg = 1.0f - tt;
        const float inv = 1.0f / (sg * sg);
        alpha_s[tid] = tt * inv;
        beta_s[tid] = 0.5f * tt * tt * inv;
    }

    const int ar = tid >> 1, akh = (tid & 1) * 16;
    const int br = tid >> 2, bk8 = (tid & 3) * 8;
    const int gn = nblk + br;
    const bool gvalid = (gn < NDIM);
    const float* xp = x + (size_t)ar * DDIM + akh;
    const float* gp = gt + (size_t)gn * DDIM + bk8;

    float acc[2][4][4];
    uint32_t ach[2][4][2];
#pragma unroll
    for (int a = 0; a < 2; a++)
#pragma unroll
        for (int b = 0; b < 4; b++) {
#pragma unroll
            for (int e = 0; e < 4; e++) acc[a][b][e] = 0.0f;
            ach[a][b][0] = 0u; ach[a][b][1] = 0u;
        }
    float g2a = 0.0f;
    float xv[16], gv[8];

#define LOAD_G1(kc)                                                        \
    do {                                                                   \
        float4 _a0 = *(const float4*)(xp + (kc));                          \
        float4 _a1 = *(const float4*)(xp + (kc) + 4);                      \
        float4 _a2 = *(const float4*)(xp + (kc) + 8);                      \
        float4 _a3 = *(const float4*)(xp + (kc) + 12);                     \
        xv[0]=_a0.x; xv[1]=_a0.y; xv[2]=_a0.z; xv[3]=_a0.w;                \
        xv[4]=_a1.x; xv[5]=_a1.y; xv[6]=_a1.z; xv[7]=_a1.w;                \
        xv[8]=_a2.x; xv[9]=_a2.y; xv[10]=_a2.z; xv[11]=_a2.w;              \
        xv[12]=_a3.x; xv[13]=_a3.y; xv[14]=_a3.z; xv[15]=_a3.w;            \
        if (gvalid) {                                                      \
            float4 _b0 = *(const float4*)(gp + (kc));                      \
            float4 _b1 = *(const float4*)(gp + (kc) + 4);                  \
            gv[0]=_b0.x; gv[1]=_b0.y; gv[2]=_b0.z; gv[3]=_b0.w;            \
            gv[4]=_b1.x; gv[5]=_b1.y; gv[6]=_b1.z; gv[7]=_b1.w;            \
        } else {                                                           \
            _Pragma("unroll") for (int _i = 0; _i < 8; _i++) gv[_i] = 0.0f;\
        }                                                                  \
    } while (0)

#define STORE_G1(pb)                                                       \
    do {                                                                   \
        _Pragma("unroll")                                                  \
        for (int _g = 0; _g < 2; _g++) {                                   \
            uint4 _uh, _ul;                                                \
            split2h_u4(xv + _g * 8, _uh, _ul);                             \
            const int _o = toff(ar, akh + _g * 8);                         \
            *(uint4*)(sm + SA1(0, pb) + _o) = _uh;                         \
            *(uint4*)(sm + SA1(1, pb) + _o) = _ul;                         \
        }                                                                  \
        {                                                                  \
            uint4 _uh, _ul;                                                \
            split2h_u4(gv, _uh, _ul);                                      \
            _Pragma("unroll") for (int _i = 0; _i < 8; _i++) g2a += gv[_i] * gv[_i]; \
            const int _o = toff(br, bk8);                                  \
            *(uint4*)(sm + SB1(0, pb) + _o) = _uh;                         \
            *(uint4*)(sm + SB1(1, pb) + _o) = _ul;                         \
        }                                                                  \
    } while (0)

    LOAD_G1(0);
    STORE_G1(0);
    __syncthreads();

    for (int c = 0; c < CH1; c++) {
        const int p = c & 1;
        const bool more = (c + 1 < CH1);
        if (more) LOAD_G1((c + 1) * KB);

        {
            uint32_t af[2][2][4];
            LOAD_AFRAGS(sm + SA1(0, p));          // xh
            MMA_PASS_F32(sm + SB1(0, p));          // xh*gh
            MMA_PASS_F16(sm + SB1(1, p));          // xh*gl
            LOAD_AFRAGS(sm + SA1(1, p));          // xl
            MMA_PASS_F16(sm + SB1(0, p));          // xl*gh
        }

        if (more) STORE_G1(p ^ 1);
        __syncthreads();
    }

    g2a += __shfl_xor_sync(0xffffffffu, g2a, 1);
    g2a += __shfl_xor_sync(0xffffffffu, g2a, 2);
    if ((tid & 3) == 0) g2s[br] = g2a;
    __syncthreads();

#pragma unroll
    for (int mt = 0; mt < 2; mt++) {
#pragma unroll
        for (int nt = 0; nt < 4; nt++) {
            const int lc = wn + nt * 8 + (lane & 3) * 2;
            const int n = nblk + lc;
            if (n >= NDIM) continue;
            const int row0 = wm + mt * 16 + (lane >> 2);
            const float a0 = alpha_s[row0], b0 = beta_s[row0];
            const float a1 = alpha_s[row0 + 8], b1 = beta_s[row0 + 8];
            const float q0 = g2s[lc], q1 = g2s[lc + 1];
            const float v00 = acc[mt][nt][0] + lo2f(ach[mt][nt][0]);
            const float v01 = acc[mt][nt][1] + hi2f(ach[mt][nt][0]);
            const float v10 = acc[mt][nt][2] + lo2f(ach[mt][nt][1]);
            const float v11 = acc[mt][nt][3] + hi2f(ach[mt][nt][1]);
            *(float2*)&g_s[(size_t)row0 * NDIM + n] = make_float2(a0 * v00 - b0 * q0, a0 * v01 - b0 * q1);
            *(float2*)&g_s[(size_t)(row0 + 8) * NDIM + n] = make_float2(a1 * v10 - b1 * q0, a1 * v11 - b1 * q1);
        }
    }
#undef LOAD_G1
#undef STORE_G1
}

// ---------------------------------------------------------------------------
// Softmax stats: rowmax; unnormalized e = exp(s-m) -> fp16; rowsum.
// ---------------------------------------------------------------------------
__global__ __launch_bounds__(256) void softmax_stats_kernel()
{
    const int b = blockIdx.x;
    const int tid = threadIdx.x;
    const float* row = g_s + (size_t)b * NDIM;
    __shared__ float red[256];

    float m = -INFINITY;
    for (int i = tid; i < NDIM; i += 256) m = fmaxf(m, row[i]);
    red[tid] = m;
    __syncthreads();
    for (int s = 128; s > 0; s >>= 1) {
        if (tid < s) red[tid] = fmaxf(red[tid], red[tid + s]);
        __syncthreads();
    }
    m = red[0];
    __syncthreads();

    float sum = 0.0f;
    for (int i = tid; i < NDIM; i += 256) {
        const float e = __expf(row[i] - m);
        sum += e;
        g_eh[(size_t)b * NDIM + i] = __float2half_rn(e);
    }
    red[tid] = sum;
    __syncthreads();
    for (int s = 128; s > 0; s >>= 1) {
        if (tid < s) red[tid] += red[tid + s];
        __syncthreads();
    }
    if (tid == 0) g_rowsum[b] = red[0];
}

// ---------------------------------------------------------------------------
// GEMM2: partial[b,d] = sum_n e[b,n]*gt[n,d].  CTA tile 128b x 64d, KB=32 (n).
// Single pass eh*gh (f32 acc). (R11 version — KB=64 rewrite regressed.)
// ---------------------------------------------------------------------------
__global__ __launch_bounds__(256, 2) void gemm2_kernel(const float* __restrict__ gt)
{
    extern __shared__ char sm[];
    const int tid = threadIdx.x, lane = tid & 31, warp = tid >> 5;
    const int wm = (warp & 3) * 32, wn = (warp >> 2) * 32;
    const int dblk = blockIdx.x * 64;
    const int nbase = blockIdx.y * SPAN2;
    const int ch = (blockIdx.y == NSPLIT - 1) ? ((NDIM - (NSPLIT - 1) * SPAN2) / KB) : (SPAN2 / KB);

    const int er = tid >> 1, ekh = (tid & 1) * 16;
    const int gn2 = (tid & 15) * 2, gdg = (tid >> 4) * 4;

    float acc[2][4][4];
#pragma unroll
    for (int a = 0; a < 2; a++)
#pragma unroll
        for (int b = 0; b < 4; b++)
#pragma unroll
            for (int e = 0; e < 4; e++) acc[a][b][e] = 0.0f;

    uint4 evh[2];
    float gva[4], gvb[4];

#define LOAD_G2(n0)                                                        \
    do {                                                                   \
        const size_t _eo = (size_t)er * NDIM + (n0) + ekh;                 \
        evh[0] = *(const uint4*)&g_eh[_eo];                                \
        evh[1] = *(const uint4*)&g_eh[_eo + 8];                            \
        float4 _f = *(const float4*)(gt + (size_t)((n0) + gn2) * DDIM + dblk + gdg);     \
        gva[0]=_f.x; gva[1]=_f.y; gva[2]=_f.z; gva[3]=_f.w;                \
        _f = *(const float4*)(gt + (size_t)((n0) + gn2 + 1) * DDIM + dblk + gdg);        \
        gvb[0]=_f.x; gvb[1]=_f.y; gvb[2]=_f.z; gvb[3]=_f.w;                \
    } while (0)

#define STORE_G2(pb)                                                       \
    do {                                                                   \
        *(uint4*)(sm + SE2(pb) + toff(er, ekh)) = evh[0];                  \
        *(uint4*)(sm + SE2(pb) + toff(er, ekh + 8)) = evh[1];              \
        _Pragma("unroll")                                                  \
        for (int _j = 0; _j < 4; _j++) {                                   \
            const int _o = toff(gdg + _j, gn2);                            \
            *(uint32_t*)(sm + SG2(pb) + _o) = pk2h(gva[_j], gvb[_j]);      \
        }                                                                  \
    } while (0)

    LOAD_G2(nbase);
    STORE_G2(0);
    __syncthreads();

    for (int c = 0; c < ch; c++) {
        const int p = c & 1;
        const bool more = (c + 1 < ch);
        if (more) LOAD_G2(nbase + (c + 1) * KB);

        {
            const char* A = sm + SE2(p);
            const char* B = sm + SG2(p);
#pragma unroll
            for (int ks = 0; ks < 2; ks++) {
                uint32_t af[2][4];
#pragma unroll
                for (int mt = 0; mt < 2; mt++) {
                    const int row = wm + mt * 16 + (lane >> 2);
                    const int kq = ks * 16 + (lane & 3) * 2;
                    af[mt][0] = *(const uint32_t*)(A + toff(row, kq));
                    af[mt][1] = *(const uint32_t*)(A + toff(row + 8, kq));
                    af[mt][2] = *(const uint32_t*)(A + toff(row, kq + 8));
                    af[mt][3] = *(const uint32_t*)(A + toff(row + 8, kq + 8));
                }
#pragma unroll
                for (int nt = 0; nt < 4; nt++) {
                    const int col = wn + nt * 8 + (lane >> 2);
                    const int kq = ks * 16 + (lane & 3) * 2;
                    uint32_t bf[2];
                    bf[0] = *(const uint32_t*)(B + toff(col, kq));
                    bf[1] = *(const uint32_t*)(B + toff(col, kq + 8));
#pragma unroll
                    for (int mt = 0; mt < 2; mt++) mma_f32acc(acc[mt][nt], af[mt], bf);
                }
            }
        }

        if (more) STORE_G2(p ^ 1);
        __syncthreads();
    }

    float* outp = g_part + (size_t)blockIdx.y * BDIM * DDIM;
#pragma unroll
    for (int mt = 0; mt < 2; mt++)
#pragma unroll
        for (int nt = 0; nt < 4; nt++) {
            const int row0 = wm + mt * 16 + (lane >> 2);
            const int col = dblk + wn + nt * 8 + (lane & 3) * 2;
            *(float2*)&outp[(size_t)row0 * DDIM + col] = make_float2(acc[mt][nt][0], acc[mt][nt][1]);
            *(float2*)&outp[(size_t)(row0 + 8) * DDIM + col] = make_float2(acc[mt][nt][2], acc[mt][nt][3]);
        }
#undef LOAD_G2
#undef STORE_G2
}

// ---------------------------------------------------------------------------
// Epilogue: out = (sum_splits partial / rowsum - x) / sig
// ---------------------------------------------------------------------------
__global__ __launch_bounds__(256) void epilogue_kernel(const float* __restrict__ x,
                                                       const float* __restrict__ t,
                                                       float* __restrict__ out)
{
    const int idx = blockIdx.x * 256 + threadIdx.x;
    if (idx >= BDIM * DDIM) return;
    const int b = idx / DDIM;
    float a = 0.0f;
#pragma unroll
    for (int s = 0; s < NSPLIT; s++) a += g_part[(size_t)s * BDIM * DDIM + idx];
    const float tt = t[b] * (1.0f / 999.0f);
    const float sg = 1.0f - tt;
    out[idx] = (a / g_rowsum[b] - x[idx]) / sg;
}

extern "C" void kernel_launch(void* const* d_in, const int* in_sizes, int n_in,
                              void* d_out, int out_size)
{
    const float* xt = (const float*)d_in[0];
    const float* t  = (const float*)d_in[1];
    const float* gt = (const float*)d_in[2];
    float* out = (float*)d_out;

    static int attr_done = 0;
    if (!attr_done) {
        cudaFuncSetAttribute(gemm1_kernel, cudaFuncAttributeMaxDynamicSharedMemorySize, SM1_TOTAL);
        cudaFuncSetAttribute(gemm2_kernel, cudaFuncAttributeMaxDynamicSharedMemorySize, SM2_TOTAL);
        attr_done = 1;
    }

    gemm1_kernel<<<NT1, 256, SM1_TOTAL>>>(xt, t, gt);
    softmax_stats_kernel<<<BDIM, 256>>>();
    dim3 g2(DT2, NSPLIT);
    gemm2_kernel<<<g2, 256, SM2_TOTAL>>>(gt);
    epilogue_kernel<<<(BDIM * DDIM + 255) / 256, 256>>>(xt, t, out);
}

// round 15
// speedup vs baseline: 1.1260x; 1.1260x over previous
#include <cuda_runtime.h>
#include <cuda_fp16.h>
#include <math.h>
#include <stdint.h>

#define NDIM 20000
#define DDIM 3072
#define BDIM 128
#define KB 32
#define KSPLIT 4
#define KSPAN (DDIM / KSPLIT)      /* 768 */
#define CH1 (KSPAN / KB)           /* 24 */
#define NT1 ((NDIM + 63) / 64)     /* 313 */
#define NSPLIT 6
#define SPAN2 3360                 /* splits 0-4: 105 chunks of 32; split 5: 3200 -> 100 */
#define DT2 (DDIM / 64)            /* 48 */

// GEMM1 smem: per buffer 2 A-splits (128x32 fp16 = 8KB) + 2 B-splits (64x32 = 4KB)
#define SA1(s, p) ((p) * 24576 + (s) * 8192)
#define SB1(s, p) ((p) * 24576 + 16384 + (s) * 4096)
#define SM1_TOTAL (2 * 24576)
// GEMM2 smem: per buffer 1 E tile (8KB) + 1 G tile (4KB)
#define SE2(p) ((p) * 12288)
#define SG2(p) ((p) * 12288 + 8192)
#define SM2_TOTAL (2 * 12288)

// Scratch (allocation-free rule: __device__ globals)
__device__ float g_dotp[KSPLIT * BDIM * NDIM];   // raw dot partials
__device__ float g_g2p[KSPLIT * NDIM];           // ||gt||^2 partials
__device__ float g_s[BDIM * NDIM];               // logits
__device__ float g_rowsum[BDIM];
__device__ __half g_eh[BDIM * NDIM];             // e = exp(s - m) in fp16
__device__ float g_part[NSPLIT * BDIM * DDIM];

// Swizzled byte offset inside a [rows x 32k] fp16 tile (row stride 64B).
__device__ __forceinline__ int toff(int row, int k)
{
    return row * 64 + ((((k >> 3) & 3) ^ ((row >> 1) & 3)) << 4) + ((k * 2) & 15);
}

__device__ __forceinline__ uint32_t pk2h(float a, float b)
{
    __half2 t = __floats2half2_rn(a, b);
    return *reinterpret_cast<uint32_t*>(&t);
}
__device__ __forceinline__ void split2h_u4(const float v[8], uint4& uh, uint4& ul)
{
    float h[8], l[8];
#pragma unroll
    for (int i = 0; i < 8; i++) {
        h[i] = __half2float(__float2half_rn(v[i]));
        l[i] = v[i] - h[i];
    }
    uh = make_uint4(pk2h(h[0], h[1]), pk2h(h[2], h[3]), pk2h(h[4], h[5]), pk2h(h[6], h[7]));
    ul = make_uint4(pk2h(l[0], l[1]), pk2h(l[2], l[3]), pk2h(l[4], l[5]), pk2h(l[6], l[7]));
}
__device__ __forceinline__ void mma_f32acc(float c[4], const uint32_t a[4], uint32_t b0, uint32_t b1)
{
    asm volatile(
        "mma.sync.aligned.m16n8k16.row.col.f32.f16.f16.f32 "
        "{%0,%1,%2,%3}, {%4,%5,%6,%7}, {%8,%9}, {%0,%1,%2,%3};"
        : "+f"(c[0]), "+f"(c[1]), "+f"(c[2]), "+f"(c[3])
        : "r"(a[0]), "r"(a[1]), "r"(a[2]), "r"(a[3]), "r"(b0), "r"(b1));
}
__device__ __forceinline__ void mma_f16acc(uint32_t c[2], const uint32_t a[4], uint32_t b0, uint32_t b1)
{
    asm volatile(
        "mma.sync.aligned.m16n8k16.row.col.f16.f16.f16.f16 "
        "{%0,%1}, {%2,%3,%4,%5}, {%6,%7}, {%0,%1};"
        : "+r"(c[0]), "+r"(c[1])
        : "r"(a[0]), "r"(a[1]), "r"(a[2]), "r"(a[3]), "r"(b0), "r"(b1));
}
__device__ __forceinline__ float lo2f(uint32_t u) { return __low2float(*reinterpret_cast<__half2*>(&u)); }
__device__ __forceinline__ float hi2f(uint32_t u) { return __high2float(*reinterpret_cast<__half2*>(&u)); }

__device__ __forceinline__ void ldsm_x4(uint32_t r[4], uint32_t addr)
{
    asm volatile("ldmatrix.sync.aligned.m8n8.x4.shared.b16 {%0,%1,%2,%3}, [%4];"
                 : "=r"(r[0]), "=r"(r[1]), "=r"(r[2]), "=r"(r[3]) : "r"(addr));
}

// ---------------------------------------------------------------------------
// GEMM1 (split-K over D): dotp[kz][b][n] = sum_{k in range} x[b,k]*gt[n,k]
// 3 passes: hh (f32 acc) + hl, lh (f16 acc). ldmatrix fragment loads.
// ---------------------------------------------------------------------------
__global__ __launch_bounds__(256, 2) void gemm1_kernel(const float* __restrict__ x,
                                                       const float* __restrict__ gt)
{
    extern __shared__ char sm[];
    const uint32_t sb = (uint32_t)__cvta_generic_to_shared(sm);

    const int tid = threadIdx.x, lane = tid & 31, warp = tid >> 5;
    const int wm = (warp & 3) * 32, wn = (warp >> 2) * 32;
    const int nblk = blockIdx.x * 64;
    const int kz = blockIdx.y;
    const int kbase = kz * KSPAN;

    // ldmatrix lane roles
    const int grp = lane >> 3, lrow = lane & 7;
    const int a_r = wm + ((grp & 1) << 3) + lrow;   // + mt*16
    const int a_k = (grp >> 1) << 3;                // + ks*16
    const int b_c = wn + ((grp >> 1) << 3) + lrow;  // + ntp*16
    const int b_k = (grp & 1) << 3;                 // + ks*16

    const int ar = tid >> 1, akh = (tid & 1) * 16;
    const int br = tid >> 2, bk8 = (tid & 3) * 8;
    const int gn = nblk + br;
    const bool gvalid = (gn < NDIM);
    const float* xp = x + (size_t)ar * DDIM + kbase + akh;
    const float* gp = gt + (size_t)gn * DDIM + kbase + bk8;

    float acc[2][4][4];
    uint32_t ach[2][4][2];
#pragma unroll
    for (int a = 0; a < 2; a++)
#pragma unroll
        for (int b = 0; b < 4; b++) {
#pragma unroll
            for (int e = 0; e < 4; e++) acc[a][b][e] = 0.0f;
            ach[a][b][0] = 0u; ach[a][b][1] = 0u;
        }
    float g2a = 0.0f;
    float xv[16], gv[8];

#define LOAD_G1(kc)                                                        \
    do {                                                                   \
        float4 _a0 = *(const float4*)(xp + (kc));                          \
        float4 _a1 = *(const float4*)(xp + (kc) + 4);                      \
        float4 _a2 = *(const float4*)(xp + (kc) + 8);                      \
        float4 _a3 = *(const float4*)(xp + (kc) + 12);                     \
        xv[0]=_a0.x; xv[1]=_a0.y; xv[2]=_a0.z; xv[3]=_a0.w;                \
        xv[4]=_a1.x; xv[5]=_a1.y; xv[6]=_a1.z; xv[7]=_a1.w;                \
        xv[8]=_a2.x; xv[9]=_a2.y; xv[10]=_a2.z; xv[11]=_a2.w;              \
        xv[12]=_a3.x; xv[13]=_a3.y; xv[14]=_a3.z; xv[15]=_a3.w;            \
        if (gvalid) {                                                      \
            float4 _b0 = *(const float4*)(gp + (kc));                      \
            float4 _b1 = *(const float4*)(gp + (kc) + 4);                  \
            gv[0]=_b0.x; gv[1]=_b0.y; gv[2]=_b0.z; gv[3]=_b0.w;            \
            gv[4]=_b1.x; gv[5]=_b1.y; gv[6]=_b1.z; gv[7]=_b1.w;            \
        } else {                                                           \
            _Pragma("unroll") for (int _i = 0; _i < 8; _i++) gv[_i] = 0.0f;\
        }                                                                  \
    } while (0)

#define STORE_G1(pb)                                                       \
    do {                                                                   \
        _Pragma("unroll")                                                  \
        for (int _g = 0; _g < 2; _g++) {                                   \
            uint4 _uh, _ul;                                                \
            split2h_u4(xv + _g * 8, _uh, _ul);                             \
            const int _o = toff(ar, akh + _g * 8);                         \
            *(uint4*)(sm + SA1(0, pb) + _o) = _uh;                         \
            *(uint4*)(sm + SA1(1, pb) + _o) = _ul;                         \
        }                                                                  \
        {                                                                  \
            uint4 _uh, _ul;                                                \
            split2h_u4(gv, _uh, _ul);                                      \
            _Pragma("unroll") for (int _i = 0; _i < 8; _i++) g2a += gv[_i] * gv[_i]; \
            const int _o = toff(br, bk8);                                  \
            *(uint4*)(sm + SB1(0, pb) + _o) = _uh;                         \
            *(uint4*)(sm + SB1(1, pb) + _o) = _ul;                         \
        }                                                                  \
    } while (0)

    LOAD_G1(0);
    STORE_G1(0);
    __syncthreads();

    for (int c = 0; c < CH1; c++) {
        const int p = c & 1;
        const bool more = (c + 1 < CH1);
        if (more) LOAD_G1((c + 1) * KB);

        {
            uint32_t af[2][2][4];
            // A = xh
#pragma unroll
            for (int mt = 0; mt < 2; mt++)
#pragma unroll
                for (int ks = 0; ks < 2; ks++)
                    ldsm_x4(af[mt][ks], sb + SA1(0, p) + toff(a_r + mt * 16, a_k + ks * 16));
#pragma unroll
            for (int ks = 0; ks < 2; ks++)
#pragma unroll
                for (int ntp = 0; ntp < 2; ntp++) {
                    uint32_t bh[4], bl[4];
                    ldsm_x4(bh, sb + SB1(0, p) + toff(b_c + ntp * 16, b_k + ks * 16));
                    ldsm_x4(bl, sb + SB1(1, p) + toff(b_c + ntp * 16, b_k + ks * 16));
#pragma unroll
                    for (int mt = 0; mt < 2; mt++) {
                        mma_f32acc(acc[mt][ntp * 2 + 0], af[mt][ks], bh[0], bh[1]);  // xh*gh
                        mma_f32acc(acc[mt][ntp * 2 + 1], af[mt][ks], bh[2], bh[3]);
                        mma_f16acc(ach[mt][ntp * 2 + 0], af[mt][ks], bl[0], bl[1]);  // xh*gl
                        mma_f16acc(ach[mt][ntp * 2 + 1], af[mt][ks], bl[2], bl[3]);
                    }
                }
            // A = xl, pass lh
#pragma unroll
            for (int mt = 0; mt < 2; mt++)
#pragma unroll
                for (int ks = 0; ks < 2; ks++)
                    ldsm_x4(af[mt][ks], sb + SA1(1, p) + toff(a_r + mt * 16, a_k + ks * 16));
#pragma unroll
            for (int ks = 0; ks < 2; ks++)
#pragma unroll
                for (int ntp = 0; ntp < 2; ntp++) {
                    uint32_t bh[4];
                    ldsm_x4(bh, sb + SB1(0, p) + toff(b_c + ntp * 16, b_k + ks * 16));
#pragma unroll
                    for (int mt = 0; mt < 2; mt++) {
                        mma_f16acc(ach[mt][ntp * 2 + 0], af[mt][ks], bh[0], bh[1]);  // xl*gh
                        mma_f16acc(ach[mt][ntp * 2 + 1], af[mt][ks], bh[2], bh[3]);
                    }
                }
        }

        if (more) STORE_G1(p ^ 1);
        __syncthreads();
    }

    g2a += __shfl_xor_sync(0xffffffffu, g2a, 1);
    g2a += __shfl_xor_sync(0xffffffffu, g2a, 2);
    if ((tid & 3) == 0 && gvalid) g_g2p[(size_t)kz * NDIM + gn] = g2a;

    float* dbase = g_dotp + (size_t)kz * BDIM * NDIM;
#pragma unroll
    for (int mt = 0; mt < 2; mt++) {
#pragma unroll
        for (int nt = 0; nt < 4; nt++) {
            const int lc = wn + nt * 8 + (lane & 3) * 2;
            const int n = nblk + lc;
            if (n >= NDIM) continue;
            const int row0 = wm + mt * 16 + (lane >> 2);
            *(float2*)&dbase[(size_t)row0 * NDIM + n] = make_float2(
                acc[mt][nt][0] + lo2f(ach[mt][nt][0]), acc[mt][nt][1] + hi2f(ach[mt][nt][0]));
            *(float2*)&dbase[(size_t)(row0 + 8) * NDIM + n] = make_float2(
                acc[mt][nt][2] + lo2f(ach[mt][nt][1]), acc[mt][nt][3] + hi2f(ach[mt][nt][1]));
        }
    }
#undef LOAD_G1
#undef STORE_G1
}

// ---------------------------------------------------------------------------
// Combine + softmax stats: s = alpha*sum(dotp) - beta*sum(g2p); rowmax;
// unnormalized e = exp(s-m) -> fp16; rowsum.
// ---------------------------------------------------------------------------
__global__ __launch_bounds__(256) void softmax_stats_kernel(const float* __restrict__ t)
{
    const int b = blockIdx.x;
    const int tid = threadIdx.x;
    __shared__ float red[256];

    const float tt = t[b] * (1.0f / 999.0f);
    const float sg = 1.0f - tt;
    const float inv = 1.0f / (sg * sg);
    const float alpha = tt * inv;
    const float beta = 0.5f * tt * tt * inv;

    const float* d0 = g_dotp + (size_t)b * NDIM;
    const float* d1 = d0 + (size_t)BDIM * NDIM;
    const float* d2 = d1 + (size_t)BDIM * NDIM;
    const float* d3 = d2 + (size_t)BDIM * NDIM;

    float m = -INFINITY;
    for (int i = tid; i < NDIM; i += 256) {
        const float dot = (d0[i] + d1[i]) + (d2[i] + d3[i]);
        const float g2 = (g_g2p[i] + g_g2p[NDIM + i]) + (g_g2p[2 * NDIM + i] + g_g2p[3 * NDIM + i]);
        const float s = alpha * dot - beta * g2;
        g_s[(size_t)b * NDIM + i] = s;
        m = fmaxf(m, s);
    }
    red[tid] = m;
    __syncthreads();
    for (int s = 128; s > 0; s >>= 1) {
        if (tid < s) red[tid] = fmaxf(red[tid], red[tid + s]);
        __syncthreads();
    }
    m = red[0];
    __syncthreads();

    float sum = 0.0f;
    for (int i = tid; i < NDIM; i += 256) {
        const float e = __expf(g_s[(size_t)b * NDIM + i] - m);
        sum += e;
        g_eh[(size_t)b * NDIM + i] = __float2half_rn(e);
    }
    red[tid] = sum;
    __syncthreads();
    for (int s = 128; s > 0; s >>= 1) {
        if (tid < s) red[tid] += red[tid + s];
        __syncthreads();
    }
    if (tid == 0) g_rowsum[b] = red[0];
}

// ---------------------------------------------------------------------------
// GEMM2: partial[b,d] = sum_n e[b,n]*gt[n,d].  CTA tile 128b x 64d, KB=32 (n).
// Single pass eh*gh (f32 acc), ldmatrix fragment loads.
// ---------------------------------------------------------------------------
__global__ __launch_bounds__(256, 2) void gemm2_kernel(const float* __restrict__ gt)
{
    extern __shared__ char sm[];
    const uint32_t sb = (uint32_t)__cvta_generic_to_shared(sm);
    const int tid = threadIdx.x, lane = tid & 31, warp = tid >> 5;
    const int wm = (warp & 3) * 32, wn = (warp >> 2) * 32;
    const int dblk = blockIdx.x * 64;
    const int nbase = blockIdx.y * SPAN2;
    const int ch = (blockIdx.y == NSPLIT - 1) ? ((NDIM - (NSPLIT - 1) * SPAN2) / KB) : (SPAN2 / KB);

    // ldmatrix lane roles
    const int grp = lane >> 3, lrow = lane & 7;
    const int a_r = wm + ((grp & 1) << 3) + lrow;
    const int a_k = (grp >> 1) << 3;
    const int b_c = wn + ((grp >> 1) << 3) + lrow;
    const int b_k = (grp & 1) << 3;

    const int er = tid >> 1, ekh = (tid & 1) * 16;
    const int gn2 = (tid & 15) * 2, gdg = (tid >> 4) * 4;

    float acc[2][4][4];
#pragma unroll
    for (int a = 0; a < 2; a++)
#pragma unroll
        for (int b = 0; b < 4; b++)
#pragma unroll
            for (int e = 0; e < 4; e++) acc[a][b][e] = 0.0f;

    uint4 evh[2];
    float gva[4], gvb[4];

#define LOAD_G2(n0)                                                        \
    do {                                                                   \
        const size_t _eo = (size_t)er * NDIM + (n0) + ekh;                 \
        evh[0] = *(const uint4*)&g_eh[_eo];                                \
        evh[1] = *(const uint4*)&g_eh[_eo + 8];                            \
        float4 _f = *(const float4*)(gt + (size_t)((n0) + gn2) * DDIM + dblk + gdg);     \
        gva[0]=_f.x; gva[1]=_f.y; gva[2]=_f.z; gva[3]=_f.w;                \
        _f = *(const float4*)(gt + (size_t)((n0) + gn2 + 1) * DDIM + dblk + gdg);        \
        gvb[0]=_f.x; gvb[1]=_f.y; gvb[2]=_f.z; gvb[3]=_f.w;                \
    } while (0)

#define STORE_G2(pb)                                                       \
    do {                                                                   \
        *(uint4*)(sm + SE2(pb) + toff(er, ekh)) = evh[0];                  \
        *(uint4*)(sm + SE2(pb) + toff(er, ekh + 8)) = evh[1];              \
        _Pragma("unroll")                                                  \
        for (int _j = 0; _j < 4; _j++) {                                   \
            const int _o = toff(gdg + _j, gn2);                            \
            *(uint32_t*)(sm + SG2(pb) + _o) = pk2h(gva[_j], gvb[_j]);      \
        }                                                                  \
    } while (0)

    LOAD_G2(nbase);
    STORE_G2(0);
    __syncthreads();

    for (int c = 0; c < ch; c++) {
        const int p = c & 1;
        const bool more = (c + 1 < ch);
        if (more) LOAD_G2(nbase + (c + 1) * KB);

        {
            uint32_t af[2][2][4];
#pragma unroll
            for (int mt = 0; mt < 2; mt++)
#pragma unroll
                for (int ks = 0; ks < 2; ks++)
                    ldsm_x4(af[mt][ks], sb + SE2(p) + toff(a_r + mt * 16, a_k + ks * 16));
#pragma unroll
            for (int ks = 0; ks < 2; ks++)
#pragma unroll
                for (int ntp = 0; ntp < 2; ntp++) {
                    uint32_t bh[4];
                    ldsm_x4(bh, sb + SG2(p) + toff(b_c + ntp * 16, b_k + ks * 16));
#pragma unroll
                    for (int mt = 0; mt < 2; mt++) {
                        mma_f32acc(acc[mt][ntp * 2 + 0], af[mt][ks], bh[0], bh[1]);
                        mma_f32acc(acc[mt][ntp * 2 + 1], af[mt][ks], bh[2], bh[3]);
                    }
                }
        }

        if (more) STORE_G2(p ^ 1);
        __syncthreads();
    }

    float* outp = g_part + (size_t)blockIdx.y * BDIM * DDIM;
#pragma unroll
    for (int mt = 0; mt < 2; mt++)
#pragma unroll
        for (int nt = 0; nt < 4; nt++) {
            const int row0 = wm + mt * 16 + (lane >> 2);
            const int col = dblk + wn + nt * 8 + (lane & 3) * 2;
            *(float2*)&outp[(size_t)row0 * DDIM + col] = make_float2(acc[mt][nt][0], acc[mt][nt][1]);
            *(float2*)&outp[(size_t)(row0 + 8) * DDIM + col] = make_float2(acc[mt][nt][2], acc[mt][nt][3]);
        }
#undef LOAD_G2
#undef STORE_G2
}

// ---------------------------------------------------------------------------
// Epilogue: out = (sum_splits partial / rowsum - x) / sig
// ---------------------------------------------------------------------------
__global__ __launch_bounds__(256) void epilogue_kernel(const float* __restrict__ x,
                                                       const float* __restrict__ t,
                                                       float* __restrict__ out)
{
    const int idx = blockIdx.x * 256 + threadIdx.x;
    if (idx >= BDIM * DDIM) return;
    const int b = idx / DDIM;
    float a = 0.0f;
#pragma unroll
    for (int s = 0; s < NSPLIT; s++) a += g_part[(size_t)s * BDIM * DDIM + idx];
    const float tt = t[b] * (1.0f / 999.0f);
    const float sg = 1.0f - tt;
    out[idx] = (a / g_rowsum[b] - x[idx]) / sg;
}

extern "C" void kernel_launch(void* const* d_in, const int* in_sizes, int n_in,
                              void* d_out, int out_size)
{
    const float* xt = (const float*)d_in[0];
    const float* t  = (const float*)d_in[1];
    const float* gt = (const float*)d_in[2];
    float* out = (float*)d_out;

    static int attr_done = 0;
    if (!attr_done) {
        cudaFuncSetAttribute(gemm1_kernel, cudaFuncAttributeMaxDynamicSharedMemorySize, SM1_TOTAL);
        cudaFuncSetAttribute(gemm2_kernel, cudaFuncAttributeMaxDynamicSharedMemorySize, SM2_TOTAL);
        attr_done = 1;
    }

    dim3 g1(NT1, KSPLIT);
    gemm1_kernel<<<g1, 256, SM1_TOTAL>>>(xt, gt);
    softmax_stats_kernel<<<BDIM, 256>>>(t);
    dim3 g2(DT2, NSPLIT);
    gemm2_kernel<<<g2, 256, SM2_TOTAL>>>(gt);
    epilogue_kernel<<<(BDIM * DDIM + 255) / 256, 256>>>(xt, t, out);
}

// round 16
// speedup vs baseline: 1.1442x; 1.0161x over previous
#include <cuda_runtime.h>
#include <cuda_fp16.h>
#include <math.h>
#include <stdint.h>

#define NDIM 20000
#define DDIM 3072
#define BDIM 128
#define KB 32
#define KSPLIT 4
#define KSPAN (DDIM / KSPLIT)      /* 768 */
#define CH1 (KSPAN / KB)           /* 24 (even) */
#define NT1 ((NDIM + 63) / 64)     /* 313 */
#define NSPLIT 6
#define SPAN2 3360                 /* splits 0-4: 105 chunks of 32; split 5: 3200 -> 100 */
#define DT2 (DDIM / 64)            /* 48 */

// GEMM1 smem: 4-deep ring, per buffer 2 A-splits (8KB) + 2 B-splits (4KB) = 24KB
#define SA1(s, p) ((p) * 24576 + (s) * 8192)
#define SB1(s, p) ((p) * 24576 + 16384 + (s) * 4096)
#define SM1_TOTAL (4 * 24576)
// GEMM2 smem: 4-deep ring, per buffer E (8KB) + G (4KB) = 12KB
#define SE2(p) ((p) * 12288)
#define SG2(p) ((p) * 12288 + 8192)
#define SM2_TOTAL (4 * 12288)

// Scratch (allocation-free rule: __device__ globals)
__device__ float g_dotp[KSPLIT * BDIM * NDIM];   // raw dot partials
__device__ float g_g2p[KSPLIT * NDIM];           // ||gt||^2 partials
__device__ float g_s[BDIM * NDIM];               // logits
__device__ float g_rowsum[BDIM];
__device__ __half g_eh[BDIM * NDIM];             // e = exp(s - m) in fp16
__device__ float g_part[NSPLIT * BDIM * DDIM];

// Swizzled byte offset inside a [rows x 32k] fp16 tile (row stride 64B).
__device__ __forceinline__ int toff(int row, int k)
{
    return row * 64 + ((((k >> 3) & 3) ^ ((row >> 1) & 3)) << 4) + ((k * 2) & 15);
}

__device__ __forceinline__ uint32_t pk2h(float a, float b)
{
    __half2 t = __floats2half2_rn(a, b);
    return *reinterpret_cast<uint32_t*>(&t);
}
__device__ __forceinline__ void split2h_u4(const float v[8], uint4& uh, uint4& ul)
{
    float h[8], l[8];
#pragma unroll
    for (int i = 0; i < 8; i++) {
        h[i] = __half2float(__float2half_rn(v[i]));
        l[i] = v[i] - h[i];
    }
    uh = make_uint4(pk2h(h[0], h[1]), pk2h(h[2], h[3]), pk2h(h[4], h[5]), pk2h(h[6], h[7]));
    ul = make_uint4(pk2h(l[0], l[1]), pk2h(l[2], l[3]), pk2h(l[4], l[5]), pk2h(l[6], l[7]));
}
__device__ __forceinline__ void mma_f32acc(float c[4], const uint32_t a[4], uint32_t b0, uint32_t b1)
{
    asm volatile(
        "mma.sync.aligned.m16n8k16.row.col.f32.f16.f16.f32 "
        "{%0,%1,%2,%3}, {%4,%5,%6,%7}, {%8,%9}, {%0,%1,%2,%3};"
        : "+f"(c[0]), "+f"(c[1]), "+f"(c[2]), "+f"(c[3])
        : "r"(a[0]), "r"(a[1]), "r"(a[2]), "r"(a[3]), "r"(b0), "r"(b1));
}
__device__ __forceinline__ void mma_f16acc(uint32_t c[2], const uint32_t a[4], uint32_t b0, uint32_t b1)
{
    asm volatile(
        "mma.sync.aligned.m16n8k16.row.col.f16.f16.f16.f16 "
        "{%0,%1}, {%2,%3,%4,%5}, {%6,%7}, {%0,%1};"
        : "+r"(c[0]), "+r"(c[1])
        : "r"(a[0]), "r"(a[1]), "r"(a[2]), "r"(a[3]), "r"(b0), "r"(b1));
}
__device__ __forceinline__ float lo2f(uint32_t u) { return __low2float(*reinterpret_cast<__half2*>(&u)); }
__device__ __forceinline__ float hi2f(uint32_t u) { return __high2float(*reinterpret_cast<__half2*>(&u)); }

__device__ __forceinline__ void ldsm_x4(uint32_t r[4], uint32_t addr)
{
    asm volatile("ldmatrix.sync.aligned.m8n8.x4.shared.b16 {%0,%1,%2,%3}, [%4];"
                 : "=r"(r[0]), "=r"(r[1]), "=r"(r[2]), "=r"(r[3]) : "r"(addr));
}

// ---------------------------------------------------------------------------
// GEMM1 (split-K over D): dotp[kz][b][n] = sum_{k in range} x[b,k]*gt[n,k]
// 3 passes: hh (f32 acc) + hl, lh (f16 acc). ldmatrix loads, 4-deep ring,
// one __syncthreads per 2 chunks.
// ---------------------------------------------------------------------------
__global__ __launch_bounds__(256, 2) void gemm1_kernel(const float* __restrict__ x,
                                                       const float* __restrict__ gt)
{
    extern __shared__ char sm[];
    const uint32_t sb = (uint32_t)__cvta_generic_to_shared(sm);

    const int tid = threadIdx.x, lane = tid & 31, warp = tid >> 5;
    const int wm = (warp & 3) * 32, wn = (warp >> 2) * 32;
    const int nblk = blockIdx.x * 64;
    const int kz = blockIdx.y;
    const int kbase = kz * KSPAN;

    // ldmatrix lane roles
    const int grp = lane >> 3, lrow = lane & 7;
    const int a_r = wm + ((grp & 1) << 3) + lrow;
    const int a_k = (grp >> 1) << 3;
    const int b_c = wn + ((grp >> 1) << 3) + lrow;
    const int b_k = (grp & 1) << 3;

    const int ar = tid >> 1, akh = (tid & 1) * 16;
    const int br = tid >> 2, bk8 = (tid & 3) * 8;
    const int gn = nblk + br;
    const bool gvalid = (gn < NDIM);
    const float* xp = x + (size_t)ar * DDIM + kbase + akh;
    const float* gp = gt + (size_t)gn * DDIM + kbase + bk8;

    float acc[2][4][4];
    uint32_t ach[2][4][2];
#pragma unroll
    for (int a = 0; a < 2; a++)
#pragma unroll
        for (int b = 0; b < 4; b++) {
#pragma unroll
            for (int e = 0; e < 4; e++) acc[a][b][e] = 0.0f;
            ach[a][b][0] = 0u; ach[a][b][1] = 0u;
        }
    float g2a = 0.0f;
    float xv[16], gv[8];

#define LOAD_G1(kc)                                                        \
    do {                                                                   \
        float4 _a0 = *(const float4*)(xp + (kc));                          \
        float4 _a1 = *(const float4*)(xp + (kc) + 4);                      \
        float4 _a2 = *(const float4*)(xp + (kc) + 8);                      \
        float4 _a3 = *(const float4*)(xp + (kc) + 12);                     \
        xv[0]=_a0.x; xv[1]=_a0.y; xv[2]=_a0.z; xv[3]=_a0.w;                \
        xv[4]=_a1.x; xv[5]=_a1.y; xv[6]=_a1.z; xv[7]=_a1.w;                \
        xv[8]=_a2.x; xv[9]=_a2.y; xv[10]=_a2.z; xv[11]=_a2.w;              \
        xv[12]=_a3.x; xv[13]=_a3.y; xv[14]=_a3.z; xv[15]=_a3.w;            \
        if (gvalid) {                                                      \
            float4 _b0 = *(const float4*)(gp + (kc));                      \
            float4 _b1 = *(const float4*)(gp + (kc) + 4);                  \
            gv[0]=_b0.x; gv[1]=_b0.y; gv[2]=_b0.z; gv[3]=_b0.w;            \
            gv[4]=_b1.x; gv[5]=_b1.y; gv[6]=_b1.z; gv[7]=_b1.w;            \
        } else {                                                           \
            _Pragma("unroll") for (int _i = 0; _i < 8; _i++) gv[_i] = 0.0f;\
        }                                                                  \
    } while (0)

#define STORE_G1(pb)                                                       \
    do {                                                                   \
        _Pragma("unroll")                                                  \
        for (int _g = 0; _g < 2; _g++) {                                   \
            uint4 _uh, _ul;                                                \
            split2h_u4(xv + _g * 8, _uh, _ul);                             \
            const int _o = toff(ar, akh + _g * 8);                         \
            *(uint4*)(sm + SA1(0, pb) + _o) = _uh;                         \
            *(uint4*)(sm + SA1(1, pb) + _o) = _ul;                         \
        }                                                                  \
        {                                                                  \
            uint4 _uh, _ul;                                                \
            split2h_u4(gv, _uh, _ul);                                      \
            _Pragma("unroll") for (int _i = 0; _i < 8; _i++) g2a += gv[_i] * gv[_i]; \
            const int _o = toff(br, bk8);                                  \
            *(uint4*)(sm + SB1(0, pb) + _o) = _uh;                         \
            *(uint4*)(sm + SB1(1, pb) + _o) = _ul;                         \
        }                                                                  \
    } while (0)

#define CONSUME_G1(pb)                                                     \
    do {                                                                   \
        uint32_t af[2][2][4];                                              \
        _Pragma("unroll")                                                  \
        for (int mt = 0; mt < 2; mt++)                                     \
            _Pragma("unroll")                                              \
            for (int ks = 0; ks < 2; ks++)                                 \
                ldsm_x4(af[mt][ks], sb + SA1(0, pb) + toff(a_r + mt * 16, a_k + ks * 16)); \
        _Pragma("unroll")                                                  \
        for (int ks = 0; ks < 2; ks++)                                     \
            _Pragma("unroll")                                              \
            for (int ntp = 0; ntp < 2; ntp++) {                            \
                uint32_t bh[4], bl[4];                                     \
                ldsm_x4(bh, sb + SB1(0, pb) + toff(b_c + ntp * 16, b_k + ks * 16)); \
                ldsm_x4(bl, sb + SB1(1, pb) + toff(b_c + ntp * 16, b_k + ks * 16)); \
                _Pragma("unroll")                                          \
                for (int mt = 0; mt < 2; mt++) {                           \
                    mma_f32acc(acc[mt][ntp * 2 + 0], af[mt][ks], bh[0], bh[1]); \
                    mma_f32acc(acc[mt][ntp * 2 + 1], af[mt][ks], bh[2], bh[3]); \
                    mma_f16acc(ach[mt][ntp * 2 + 0], af[mt][ks], bl[0], bl[1]); \
                    mma_f16acc(ach[mt][ntp * 2 + 1], af[mt][ks], bl[2], bl[3]); \
                }                                                          \
            }                                                              \
        _Pragma("unroll")                                                  \
        for (int mt = 0; mt < 2; mt++)                                     \
            _Pragma("unroll")                                              \
            for (int ks = 0; ks < 2; ks++)                                 \
                ldsm_x4(af[mt][ks], sb + SA1(1, pb) + toff(a_r + mt * 16, a_k + ks * 16)); \
        _Pragma("unroll")                                                  \
        for (int ks = 0; ks < 2; ks++)                                     \
            _Pragma("unroll")                                              \
            for (int ntp = 0; ntp < 2; ntp++) {                            \
                uint32_t bh[4];                                            \
                ldsm_x4(bh, sb + SB1(0, pb) + toff(b_c + ntp * 16, b_k + ks * 16)); \
                _Pragma("unroll")                                          \
                for (int mt = 0; mt < 2; mt++) {                           \
                    mma_f16acc(ach[mt][ntp * 2 + 0], af[mt][ks], bh[0], bh[1]); \
                    mma_f16acc(ach[mt][ntp * 2 + 1], af[mt][ks], bh[2], bh[3]); \
                }                                                          \
            }                                                              \
    } while (0)

    // Prologue: fill buffers 0 and 1.
    LOAD_G1(0);
    STORE_G1(0);
    LOAD_G1(KB);
    STORE_G1(1);
    __syncthreads();

    for (int cc = 0; cc < CH1; cc += 2) {
        if (cc + 2 < CH1) {
            LOAD_G1((cc + 2) * KB);
            CONSUME_G1((cc) & 3);
            STORE_G1((cc + 2) & 3);
        } else {
            CONSUME_G1((cc) & 3);
        }
        if (cc + 3 < CH1) {
            LOAD_G1((cc + 3) * KB);
            CONSUME_G1((cc + 1) & 3);
            STORE_G1((cc + 3) & 3);
        } else if (cc + 1 < CH1) {
            CONSUME_G1((cc + 1) & 3);
        }
        __syncthreads();
    }

    g2a += __shfl_xor_sync(0xffffffffu, g2a, 1);
    g2a += __shfl_xor_sync(0xffffffffu, g2a, 2);
    if ((tid & 3) == 0 && gvalid) g_g2p[(size_t)kz * NDIM + gn] = g2a;

    float* dbase = g_dotp + (size_t)kz * BDIM * NDIM;
#pragma unroll
    for (int mt = 0; mt < 2; mt++) {
#pragma unroll
        for (int nt = 0; nt < 4; nt++) {
            const int lc = wn + nt * 8 + (lane & 3) * 2;
            const int n = nblk + lc;
            if (n >= NDIM) continue;
            const int row0 = wm + mt * 16 + (lane >> 2);
            *(float2*)&dbase[(size_t)row0 * NDIM + n] = make_float2(
                acc[mt][nt][0] + lo2f(ach[mt][nt][0]), acc[mt][nt][1] + hi2f(ach[mt][nt][0]));
            *(float2*)&dbase[(size_t)(row0 + 8) * NDIM + n] = make_float2(
                acc[mt][nt][2] + lo2f(ach[mt][nt][1]), acc[mt][nt][3] + hi2f(ach[mt][nt][1]));
        }
    }
#undef LOAD_G1
#undef STORE_G1
#undef CONSUME_G1
}

// ---------------------------------------------------------------------------
// Combine + softmax stats: s = alpha*sum(dotp) - beta*sum(g2p); rowmax;
// unnormalized e = exp(s-m) -> fp16; rowsum.
// ---------------------------------------------------------------------------
__global__ __launch_bounds__(256) void softmax_stats_kernel(const float* __restrict__ t)
{
    const int b = blockIdx.x;
    const int tid = threadIdx.x;
    __shared__ float red[256];

    const float tt = t[b] * (1.0f / 999.0f);
    const float sg = 1.0f - tt;
    const float inv = 1.0f / (sg * sg);
    const float alpha = tt * inv;
    const float beta = 0.5f * tt * tt * inv;

    const float* d0 = g_dotp + (size_t)b * NDIM;
    const float* d1 = d0 + (size_t)BDIM * NDIM;
    const float* d2 = d1 + (size_t)BDIM * NDIM;
    const float* d3 = d2 + (size_t)BDIM * NDIM;

    float m = -INFINITY;
    for (int i = tid; i < NDIM; i += 256) {
        const float dot = (d0[i] + d1[i]) + (d2[i] + d3[i]);
        const float g2 = (g_g2p[i] + g_g2p[NDIM + i]) + (g_g2p[2 * NDIM + i] + g_g2p[3 * NDIM + i]);
        const float s = alpha * dot - beta * g2;
        g_s[(size_t)b * NDIM + i] = s;
        m = fmaxf(m, s);
    }
    red[tid] = m;
    __syncthreads();
    for (int s = 128; s > 0; s >>= 1) {
        if (tid < s) red[tid] = fmaxf(red[tid], red[tid + s]);
        __syncthreads();
    }
    m = red[0];
    __syncthreads();

    float sum = 0.0f;
    for (int i = tid; i < NDIM; i += 256) {
        const float e = __expf(g_s[(size_t)b * NDIM + i] - m);
        sum += e;
        g_eh[(size_t)b * NDIM + i] = __float2half_rn(e);
    }
    red[tid] = sum;
    __syncthreads();
    for (int s = 128; s > 0; s >>= 1) {
        if (tid < s) red[tid] += red[tid + s];
        __syncthreads();
    }
    if (tid == 0) g_rowsum[b] = red[0];
}

// ---------------------------------------------------------------------------
// GEMM2: partial[b,d] = sum_n e[b,n]*gt[n,d].  CTA tile 128b x 64d, KB=32 (n).
// Single pass eh*gh (f32 acc), ldmatrix loads, 4-deep ring, bar per 2 chunks.
// ---------------------------------------------------------------------------
__global__ __launch_bounds__(256, 2) void gemm2_kernel(const float* __restrict__ gt)
{
    extern __shared__ char sm[];
    const uint32_t sb = (uint32_t)__cvta_generic_to_shared(sm);
    const int tid = threadIdx.x, lane = tid & 31, warp = tid >> 5;
    const int wm = (warp & 3) * 32, wn = (warp >> 2) * 32;
    const int dblk = blockIdx.x * 64;
    const int nbase = blockIdx.y * SPAN2;
    const int ch = (blockIdx.y == NSPLIT - 1) ? ((NDIM - (NSPLIT - 1) * SPAN2) / KB) : (SPAN2 / KB);

    const int grp = lane >> 3, lrow = lane & 7;
    const int a_r = wm + ((grp & 1) << 3) + lrow;
    const int a_k = (grp >> 1) << 3;
    const int b_c = wn + ((grp >> 1) << 3) + lrow;
    const int b_k = (grp & 1) << 3;

    const int er = tid >> 1, ekh = (tid & 1) * 16;
    const int gn2 = (tid & 15) * 2, gdg = (tid >> 4) * 4;

    float acc[2][4][4];
#pragma unroll
    for (int a = 0; a < 2; a++)
#pragma unroll
        for (int b = 0; b < 4; b++)
#pragma unroll
            for (int e = 0; e < 4; e++) acc[a][b][e] = 0.0f;

    uint4 evh[2];
    float gva[4], gvb[4];

#define LOAD_G2(n0)                                                        \
    do {                                                                   \
        const size_t _eo = (size_t)er * NDIM + (n0) + ekh;                 \
        evh[0] = *(const uint4*)&g_eh[_eo];                                \
        evh[1] = *(const uint4*)&g_eh[_eo + 8];                            \
        float4 _f = *(const float4*)(gt + (size_t)((n0) + gn2) * DDIM + dblk + gdg);     \
        gva[0]=_f.x; gva[1]=_f.y; gva[2]=_f.z; gva[3]=_f.w;                \
        _f = *(const float4*)(gt + (size_t)((n0) + gn2 + 1) * DDIM + dblk + gdg);        \
        gvb[0]=_f.x; gvb[1]=_f.y; gvb[2]=_f.z; gvb[3]=_f.w;                \
    } while (0)

#define STORE_G2(pb)                                                       \
    do {                                                                   \
        *(uint4*)(sm + SE2(pb) + toff(er, ekh)) = evh[0];                  \
        *(uint4*)(sm + SE2(pb) + toff(er, ekh + 8)) = evh[1];              \
        _Pragma("unroll")                                                  \
        for (int _j = 0; _j < 4; _j++) {                                   \
            const int _o = toff(gdg + _j, gn2);                            \
            *(uint32_t*)(sm + SG2(pb) + _o) = pk2h(gva[_j], gvb[_j]);      \
        }                                                                  \
    } while (0)

#define CONSUME_G2(pb)                                                     \
    do {                                                                   \
        uint32_t af[2][2][4];                                              \
        _Pragma("unroll")                                                  \
        for (int mt = 0; mt < 2; mt++)                                     \
            _Pragma("unroll")                                              \
            for (int ks = 0; ks < 2; ks++)                                 \
                ldsm_x4(af[mt][ks], sb + SE2(pb) + toff(a_r + mt * 16, a_k + ks * 16)); \
        _Pragma("unroll")                                                  \
        for (int ks = 0; ks < 2; ks++)                                     \
            _Pragma("unroll")                                              \
            for (int ntp = 0; ntp < 2; ntp++) {                            \
                uint32_t bh[4];                                            \
                ldsm_x4(bh, sb + SG2(pb) + toff(b_c + ntp * 16, b_k + ks * 16)); \
                _Pragma("unroll")                                          \
                for (int mt = 0; mt < 2; mt++) {                           \
                    mma_f32acc(acc[mt][ntp * 2 + 0], af[mt][ks], bh[0], bh[1]); \
                    mma_f32acc(acc[mt][ntp * 2 + 1], af[mt][ks], bh[2], bh[3]); \
                }                                                          \
            }                                                              \
    } while (0)

    // Prologue: fill buffers 0 and 1.
    LOAD_G2(nbase);
    STORE_G2(0);
    LOAD_G2(nbase + KB);
    STORE_G2(1);
    __syncthreads();

    for (int cc = 0; cc < ch; cc += 2) {
        if (cc + 2 < ch) {
            LOAD_G2(nbase + (cc + 2) * KB);
            CONSUME_G2((cc) & 3);
            STORE_G2((cc + 2) & 3);
        } else {
            CONSUME_G2((cc) & 3);
        }
        if (cc + 3 < ch) {
            LOAD_G2(nbase + (cc + 3) * KB);
            CONSUME_G2((cc + 1) & 3);
            STORE_G2((cc + 3) & 3);
        } else if (cc + 1 < ch) {
            CONSUME_G2((cc + 1) & 3);
        }
        __syncthreads();
    }

    float* outp = g_part + (size_t)blockIdx.y * BDIM * DDIM;
#pragma unroll
    for (int mt = 0; mt < 2; mt++)
#pragma unroll
        for (int nt = 0; nt < 4; nt++) {
            const int row0 = wm + mt * 16 + (lane >> 2);
            const int col = dblk + wn + nt * 8 + (lane & 3) * 2;
            *(float2*)&outp[(size_t)row0 * DDIM + col] = make_float2(acc[mt][nt][0], acc[mt][nt][1]);
            *(float2*)&outp[(size_t)(row0 + 8) * DDIM + col] = make_float2(acc[mt][nt][2], acc[mt][nt][3]);
        }
#undef LOAD_G2
#undef STORE_G2
#undef CONSUME_G2
}

// ---------------------------------------------------------------------------
// Epilogue: out = (sum_splits partial / rowsum - x) / sig
// ---------------------------------------------------------------------------
__global__ __launch_bounds__(256) void epilogue_kernel(const float* __restrict__ x,
                                                       const float* __restrict__ t,
                                                       float* __restrict__ out)
{
    const int idx = blockIdx.x * 256 + threadIdx.x;
    if (idx >= BDIM * DDIM) return;
    const int b = idx / DDIM;
    float a = 0.0f;
#pragma unroll
    for (int s = 0; s < NSPLIT; s++) a += g_part[(size_t)s * BDIM * DDIM + idx];
    const float tt = t[b] * (1.0f / 999.0f);
    const float sg = 1.0f - tt;
    out[idx] = (a / g_rowsum[b] - x[idx]) / sg;
}

extern "C" void kernel_launch(void* const* d_in, const int* in_sizes, int n_in,
                              void* d_out, int out_size)
{
    const float* xt = (const float*)d_in[0];
    const float* t  = (const float*)d_in[1];
    const float* gt = (const float*)d_in[2];
    float* out = (float*)d_out;

    static int attr_done = 0;
    if (!attr_done) {
        cudaFuncSetAttribute(gemm1_kernel, cudaFuncAttributeMaxDynamicSharedMemorySize, SM1_TOTAL);
        cudaFuncSetAttribute(gemm2_kernel, cudaFuncAttributeMaxDynamicSharedMemorySize, SM2_TOTAL);
        attr_done = 1;
    }

    dim3 g1(NT1, KSPLIT);
    gemm1_kernel<<<g1, 256, SM1_TOTAL>>>(xt, gt);
    softmax_stats_kernel<<<BDIM, 256>>>(t);
    dim3 g2(DT2, NSPLIT);
    gemm2_kernel<<<g2, 256, SM2_TOTAL>>>(gt);
    epilogue_kernel<<<(BDIM * DDIM + 255) / 256, 256>>>(xt, t, out);
}